// round 1
// baseline (speedup 1.0000x reference)
#include <cuda_runtime.h>
#include <cuda_bf16.h>
#include <math.h>

#define BATCH 128
#define HH 256
#define WW 256
#define HW (HH*WW)
#define NK 68
#define OFFSET_SCALE 6.0f

// per-batch transform params: M[0..8] row-major (e,d), t[9..11]
__device__ float g_par[BATCH][12];

// ---------------------------------------------------------------------------
// Kernel 1: per-batch Kabsch (similarity transform) via Newton polar iteration
// ---------------------------------------------------------------------------
__global__ void kabsch_kernel(const float* __restrict__ Offset,
                              const float* __restrict__ Pos,
                              const float* __restrict__ meanp,
                              const int*   __restrict__ uv)
{
    int b   = blockIdx.x;
    int tid = threadIdx.x;

    __shared__ float  s_src[NK][3];
    __shared__ float  s_dst[NK][3];
    __shared__ double s_acc[17];   // [0]=s1 [1]=s2 [2..4]=sum_src [5..7]=sum_dst [8..16]=X

    if (tid < 17) s_acc[tid] = 0.0;
    __syncthreads();

    if (tid < NK) {
        int u0 = uv[2*tid];
        int u1 = uv[2*tid + 1];
        int idx = u0 * WW + u1;
        const float* ob = Offset + (size_t)b * 3 * HW;
        const float* pb = Pos    + (size_t)b * 3 * HW;
        #pragma unroll
        for (int c = 0; c < 3; c++) {
            s_src[tid][c] = ob[c*HW + idx] * OFFSET_SCALE + meanp[c*HW + idx];
            s_dst[tid][c] = pb[c*HW + idx];
        }
    }
    __syncthreads();

    // phase 1: s1 = sum ||src_i - src_0||, s2 = sum ||dst_i - dst_0||, sums
    if (tid < NK) {
        double dsx = (double)s_src[tid][0] - (double)s_src[0][0];
        double dsy = (double)s_src[tid][1] - (double)s_src[0][1];
        double dsz = (double)s_src[tid][2] - (double)s_src[0][2];
        double ddx = (double)s_dst[tid][0] - (double)s_dst[0][0];
        double ddy = (double)s_dst[tid][1] - (double)s_dst[0][1];
        double ddz = (double)s_dst[tid][2] - (double)s_dst[0][2];
        double n1 = sqrt(dsx*dsx + dsy*dsy + dsz*dsz);
        double n2 = sqrt(ddx*ddx + ddy*ddy + ddz*ddz);
        atomicAdd(&s_acc[0], n1);
        atomicAdd(&s_acc[1], n2);
        atomicAdd(&s_acc[2], (double)s_src[tid][0]);
        atomicAdd(&s_acc[3], (double)s_src[tid][1]);
        atomicAdd(&s_acc[4], (double)s_src[tid][2]);
        atomicAdd(&s_acc[5], (double)s_dst[tid][0]);
        atomicAdd(&s_acc[6], (double)s_dst[tid][1]);
        atomicAdd(&s_acc[7], (double)s_dst[tid][2]);
    }
    __syncthreads();

    double scale = s_acc[1] / s_acc[0];
    double msrc[3], mdst[3];
    #pragma unroll
    for (int c = 0; c < 3; c++) {
        msrc[c] = s_acc[2+c] / (double)NK;
        mdst[c] = s_acc[5+c] / (double)NK;
    }

    // phase 2: X[e][d] = sum_i (dst_i - mdst)[e] * (src_i - msrc)[d]
    // (scale > 0 factor dropped: doesn't change the polar orthogonal factor)
    if (tid < NK) {
        double sd[3], dd[3];
        #pragma unroll
        for (int c = 0; c < 3; c++) {
            sd[c] = (double)s_src[tid][c] - msrc[c];
            dd[c] = (double)s_dst[tid][c] - mdst[c];
        }
        #pragma unroll
        for (int e = 0; e < 3; e++)
            #pragma unroll
            for (int d = 0; d < 3; d++)
                atomicAdd(&s_acc[8 + e*3 + d], dd[e] * sd[d]);
    }
    __syncthreads();

    if (tid == 0) {
        // Newton polar iteration with gamma scaling:
        //   Q <- 0.5 * (g*Q + (1/g) * Q^{-T}),  g = (||Q^{-1}||_F / ||Q||_F)^{1/2}
        // Converges to the orthogonal polar factor of X = H^T,
        // which equals Kabsch's R = V U^T (sign-consistent, det-preserving).
        double q[9];
        #pragma unroll
        for (int i = 0; i < 9; i++) q[i] = s_acc[8 + i];

        for (int it = 0; it < 25; it++) {
            double c00 =  q[4]*q[8] - q[5]*q[7];
            double c01 = -(q[3]*q[8] - q[5]*q[6]);
            double c02 =  q[3]*q[7] - q[4]*q[6];
            double det = q[0]*c00 + q[1]*c01 + q[2]*c02;
            double inv[9]; // inv = adj(Q)/det, row-major
            inv[0] =  c00 / det;
            inv[1] = (q[2]*q[7] - q[1]*q[8]) / det;
            inv[2] = (q[1]*q[5] - q[2]*q[4]) / det;
            inv[3] =  c01 / det;
            inv[4] = (q[0]*q[8] - q[2]*q[6]) / det;
            inv[5] = (q[2]*q[3] - q[0]*q[5]) / det;
            inv[6] =  c02 / det;
            inv[7] = (q[1]*q[6] - q[0]*q[7]) / det;
            inv[8] = (q[0]*q[4] - q[1]*q[3]) / det;

            double nq = 0.0, ni = 0.0;
            #pragma unroll
            for (int i = 0; i < 9; i++) { nq += q[i]*q[i]; ni += inv[i]*inv[i]; }
            double g  = sqrt(sqrt(ni / nq));   // (||inv||_F/||Q||_F)^{1/2}
            double gi = 0.5 / g;
            g *= 0.5;
            // Q <- 0.5*(g*Q + (1/g)*inv^T)
            double nq2[9];
            #pragma unroll
            for (int r = 0; r < 3; r++)
                #pragma unroll
                for (int c = 0; c < 3; c++)
                    nq2[r*3+c] = g * q[r*3+c] + gi * inv[c*3+r];
            #pragma unroll
            for (int i = 0; i < 9; i++) q[i] = nq2[i];
        }

        // M = scale * R ; t[e] = mdst[e] - sum_d M[e][d]*msrc[d]
        #pragma unroll
        for (int i = 0; i < 9; i++) g_par[b][i] = (float)(scale * q[i]);
        #pragma unroll
        for (int e = 0; e < 3; e++) {
            double t = mdst[e] - scale * (q[e*3+0]*msrc[0] + q[e*3+1]*msrc[1] + q[e*3+2]*msrc[2]);
            g_par[b][9 + e] = (float)t;
        }
    }
}

// ---------------------------------------------------------------------------
// Kernel 2: apply affine transform to all pixels (float4-vectorized, streaming)
// out[b,e,p] = sum_d M[e][d] * (6*Offset[b,d,p] + mean[d,p]) + t[e]
// ---------------------------------------------------------------------------
__global__ void __launch_bounds__(256) apply_kernel(
    const float4* __restrict__ Offset,
    const float4* __restrict__ meanp,
    float4* __restrict__ out)
{
    const int b = blockIdx.y;
    const int i = blockIdx.x * blockDim.x + threadIdx.x;  // 0 .. HW/4-1

    __shared__ float sP[12];
    if (threadIdx.x < 12) sP[threadIdx.x] = g_par[b][threadIdx.x];
    __syncthreads();

    const int planeQ = HW / 4;
    const size_t base = (size_t)b * 3 * planeQ;

    float4 o0 = Offset[base + 0*planeQ + i];
    float4 o1 = Offset[base + 1*planeQ + i];
    float4 o2 = Offset[base + 2*planeQ + i];
    float4 m0 = meanp[0*planeQ + i];
    float4 m1 = meanp[1*planeQ + i];
    float4 m2 = meanp[2*planeQ + i];

    float4 p0, p1, p2;
    p0.x = fmaf(o0.x, OFFSET_SCALE, m0.x); p0.y = fmaf(o0.y, OFFSET_SCALE, m0.y);
    p0.z = fmaf(o0.z, OFFSET_SCALE, m0.z); p0.w = fmaf(o0.w, OFFSET_SCALE, m0.w);
    p1.x = fmaf(o1.x, OFFSET_SCALE, m1.x); p1.y = fmaf(o1.y, OFFSET_SCALE, m1.y);
    p1.z = fmaf(o1.z, OFFSET_SCALE, m1.z); p1.w = fmaf(o1.w, OFFSET_SCALE, m1.w);
    p2.x = fmaf(o2.x, OFFSET_SCALE, m2.x); p2.y = fmaf(o2.y, OFFSET_SCALE, m2.y);
    p2.z = fmaf(o2.z, OFFSET_SCALE, m2.z); p2.w = fmaf(o2.w, OFFSET_SCALE, m2.w);

    #pragma unroll
    for (int e = 0; e < 3; e++) {
        float a = sP[e*3+0], bb = sP[e*3+1], cc = sP[e*3+2], t = sP[9+e];
        float4 r;
        r.x = fmaf(a, p0.x, fmaf(bb, p1.x, fmaf(cc, p2.x, t)));
        r.y = fmaf(a, p0.y, fmaf(bb, p1.y, fmaf(cc, p2.y, t)));
        r.z = fmaf(a, p0.z, fmaf(bb, p1.z, fmaf(cc, p2.z, t)));
        r.w = fmaf(a, p0.w, fmaf(bb, p1.w, fmaf(cc, p2.w, t)));
        out[base + e*planeQ + i] = r;
    }
}

// ---------------------------------------------------------------------------
extern "C" void kernel_launch(void* const* d_in, const int* in_sizes, int n_in,
                              void* d_out, int out_size)
{
    const float* Offset = (const float*)d_in[0];  // (128,3,256,256)
    const float* Pos    = (const float*)d_in[1];  // (128,3,256,256)
    const float* meanp  = (const float*)d_in[2];  // (3,256,256)
    const int*   uv     = (const int*)  d_in[3];  // (68,2)
    float* out = (float*)d_out;

    kabsch_kernel<<<BATCH, 128>>>(Offset, Pos, meanp, uv);

    dim3 grid(HW / 4 / 256, BATCH);
    apply_kernel<<<grid, 256>>>((const float4*)Offset, (const float4*)meanp, (float4*)out);
}

// round 2
// speedup vs baseline: 2.7373x; 2.7373x over previous
#include <cuda_runtime.h>
#include <cuda_bf16.h>
#include <math.h>

#define BATCH 128
#define HH 256
#define WW 256
#define HW (HH*WW)
#define NK 68
#define OFFSET_SCALE 6.0f

// per-batch transform params: M[0..8] row-major (e,d), t[9..11]
__device__ float g_par[BATCH][12];

// ---------------------------------------------------------------------------
// Kernel 1: per-batch Kabsch (similarity transform) via fp32 Newton polar
// ---------------------------------------------------------------------------
__global__ void kabsch_kernel(const float* __restrict__ Offset,
                              const float* __restrict__ Pos,
                              const float* __restrict__ meanp,
                              const int*   __restrict__ uv)
{
    int b   = blockIdx.x;
    int tid = threadIdx.x;

    __shared__ float s_src[NK][3];
    __shared__ float s_dst[NK][3];
    __shared__ float s_acc[17];   // [0]=s1 [1]=s2 [2..4]=sum_src [5..7]=sum_dst [8..16]=X

    if (tid < 17) s_acc[tid] = 0.0f;
    __syncthreads();

    if (tid < NK) {
        int u0 = uv[2*tid];
        int u1 = uv[2*tid + 1];
        int idx = u0 * WW + u1;
        const float* ob = Offset + (size_t)b * 3 * HW;
        const float* pb = Pos    + (size_t)b * 3 * HW;
        #pragma unroll
        for (int c = 0; c < 3; c++) {
            s_src[tid][c] = fmaf(ob[c*HW + idx], OFFSET_SCALE, meanp[c*HW + idx]);
            s_dst[tid][c] = pb[c*HW + idx];
        }
    }
    __syncthreads();

    // phase 1: s1 = sum ||src_i - src_0||, s2 = sum ||dst_i - dst_0||, sums
    if (tid < NK) {
        float dsx = s_src[tid][0] - s_src[0][0];
        float dsy = s_src[tid][1] - s_src[0][1];
        float dsz = s_src[tid][2] - s_src[0][2];
        float ddx = s_dst[tid][0] - s_dst[0][0];
        float ddy = s_dst[tid][1] - s_dst[0][1];
        float ddz = s_dst[tid][2] - s_dst[0][2];
        float n1 = sqrtf(fmaf(dsx,dsx, fmaf(dsy,dsy, dsz*dsz)));
        float n2 = sqrtf(fmaf(ddx,ddx, fmaf(ddy,ddy, ddz*ddz)));
        atomicAdd(&s_acc[0], n1);
        atomicAdd(&s_acc[1], n2);
        atomicAdd(&s_acc[2], s_src[tid][0]);
        atomicAdd(&s_acc[3], s_src[tid][1]);
        atomicAdd(&s_acc[4], s_src[tid][2]);
        atomicAdd(&s_acc[5], s_dst[tid][0]);
        atomicAdd(&s_acc[6], s_dst[tid][1]);
        atomicAdd(&s_acc[7], s_dst[tid][2]);
    }
    __syncthreads();

    float scale = s_acc[1] / s_acc[0];
    float msrc[3], mdst[3];
    #pragma unroll
    for (int c = 0; c < 3; c++) {
        msrc[c] = s_acc[2+c] * (1.0f / NK);
        mdst[c] = s_acc[5+c] * (1.0f / NK);
    }

    // phase 2: X[e][d] = sum_i (dst_i - mdst)[e] * (src_i - msrc)[d]  (= H^T)
    if (tid < NK) {
        float sd[3], dd[3];
        #pragma unroll
        for (int c = 0; c < 3; c++) {
            sd[c] = s_src[tid][c] - msrc[c];
            dd[c] = s_dst[tid][c] - mdst[c];
        }
        #pragma unroll
        for (int e = 0; e < 3; e++)
            #pragma unroll
            for (int d = 0; d < 3; d++)
                atomicAdd(&s_acc[8 + e*3 + d], dd[e] * sd[d]);
    }
    __syncthreads();

    if (tid == 0) {
        // Newton polar iteration with gamma scaling:
        //   Q <- 0.5*(g*Q + (1/g)*Q^{-T}),  g = (||Q^{-1}||_F / ||Q||_F)^{1/2}
        // Converges (quadratically, self-correcting) to the orthogonal polar
        // factor of X = H^T, which equals Kabsch's R = V U^T.
        float q[9];
        #pragma unroll
        for (int i = 0; i < 9; i++) q[i] = s_acc[8 + i];

        #pragma unroll 1
        for (int it = 0; it < 16; it++) {
            float c00 =  q[4]*q[8] - q[5]*q[7];
            float c01 = -(q[3]*q[8] - q[5]*q[6]);
            float c02 =  q[3]*q[7] - q[4]*q[6];
            float det = q[0]*c00 + q[1]*c01 + q[2]*c02;
            float rdet = __fdividef(1.0f, det);
            float inv[9]; // inv = adj(Q)/det, row-major
            inv[0] =  c00 * rdet;
            inv[1] = (q[2]*q[7] - q[1]*q[8]) * rdet;
            inv[2] = (q[1]*q[5] - q[2]*q[4]) * rdet;
            inv[3] =  c01 * rdet;
            inv[4] = (q[0]*q[8] - q[2]*q[6]) * rdet;
            inv[5] = (q[2]*q[3] - q[0]*q[5]) * rdet;
            inv[6] =  c02 * rdet;
            inv[7] = (q[1]*q[6] - q[0]*q[7]) * rdet;
            inv[8] = (q[0]*q[4] - q[1]*q[3]) * rdet;

            float nq = 0.0f, ni = 0.0f;
            #pragma unroll
            for (int i = 0; i < 9; i++) { nq = fmaf(q[i], q[i], nq); ni = fmaf(inv[i], inv[i], ni); }
            float g  = sqrtf(sqrtf(__fdividef(ni, nq)));   // (||inv||_F/||Q||_F)^{1/2}
            float gi = 0.5f * __fdividef(1.0f, g);
            g *= 0.5f;
            // Q <- 0.5*(g*Q + (1/g)*inv^T)
            float nq2[9];
            #pragma unroll
            for (int r = 0; r < 3; r++)
                #pragma unroll
                for (int c = 0; c < 3; c++)
                    nq2[r*3+c] = fmaf(g, q[r*3+c], gi * inv[c*3+r]);
            #pragma unroll
            for (int i = 0; i < 9; i++) q[i] = nq2[i];
        }

        // M = scale * R ; t[e] = mdst[e] - sum_d M[e][d]*msrc[d]
        #pragma unroll
        for (int i = 0; i < 9; i++) g_par[b][i] = scale * q[i];
        #pragma unroll
        for (int e = 0; e < 3; e++) {
            float t = mdst[e] - scale * (q[e*3+0]*msrc[0] + q[e*3+1]*msrc[1] + q[e*3+2]*msrc[2]);
            g_par[b][9 + e] = t;
        }
    }
}

// ---------------------------------------------------------------------------
// Kernel 2: apply affine transform to all pixels (float4-vectorized, streaming)
// out[b,e,p] = sum_d M[e][d] * (6*Offset[b,d,p] + mean[d,p]) + t[e]
// ---------------------------------------------------------------------------
__global__ void __launch_bounds__(256) apply_kernel(
    const float4* __restrict__ Offset,
    const float4* __restrict__ meanp,
    float4* __restrict__ out)
{
    const int b = blockIdx.y;
    const int i = blockIdx.x * blockDim.x + threadIdx.x;  // 0 .. HW/4-1

    __shared__ float sP[12];
    if (threadIdx.x < 12) sP[threadIdx.x] = g_par[b][threadIdx.x];
    __syncthreads();

    const int planeQ = HW / 4;
    const size_t base = (size_t)b * 3 * planeQ;

    // Offset: streamed once per batch, no reuse -> evict-first (.cs)
    float4 o0 = __ldcs(&Offset[base + 0*planeQ + i]);
    float4 o1 = __ldcs(&Offset[base + 1*planeQ + i]);
    float4 o2 = __ldcs(&Offset[base + 2*planeQ + i]);
    // mean: reused by all 128 batches -> keep cacheable
    float4 m0 = __ldg(&meanp[0*planeQ + i]);
    float4 m1 = __ldg(&meanp[1*planeQ + i]);
    float4 m2 = __ldg(&meanp[2*planeQ + i]);

    float4 p0, p1, p2;
    p0.x = fmaf(o0.x, OFFSET_SCALE, m0.x); p0.y = fmaf(o0.y, OFFSET_SCALE, m0.y);
    p0.z = fmaf(o0.z, OFFSET_SCALE, m0.z); p0.w = fmaf(o0.w, OFFSET_SCALE, m0.w);
    p1.x = fmaf(o1.x, OFFSET_SCALE, m1.x); p1.y = fmaf(o1.y, OFFSET_SCALE, m1.y);
    p1.z = fmaf(o1.z, OFFSET_SCALE, m1.z); p1.w = fmaf(o1.w, OFFSET_SCALE, m1.w);
    p2.x = fmaf(o2.x, OFFSET_SCALE, m2.x); p2.y = fmaf(o2.y, OFFSET_SCALE, m2.y);
    p2.z = fmaf(o2.z, OFFSET_SCALE, m2.z); p2.w = fmaf(o2.w, OFFSET_SCALE, m2.w);

    #pragma unroll
    for (int e = 0; e < 3; e++) {
        float a = sP[e*3+0], bb = sP[e*3+1], cc = sP[e*3+2], t = sP[9+e];
        float4 r;
        r.x = fmaf(a, p0.x, fmaf(bb, p1.x, fmaf(cc, p2.x, t)));
        r.y = fmaf(a, p0.y, fmaf(bb, p1.y, fmaf(cc, p2.y, t)));
        r.z = fmaf(a, p0.z, fmaf(bb, p1.z, fmaf(cc, p2.z, t)));
        r.w = fmaf(a, p0.w, fmaf(bb, p1.w, fmaf(cc, p2.w, t)));
        __stcs(&out[base + e*planeQ + i], r);
    }
}

// ---------------------------------------------------------------------------
extern "C" void kernel_launch(void* const* d_in, const int* in_sizes, int n_in,
                              void* d_out, int out_size)
{
    const float* Offset = (const float*)d_in[0];  // (128,3,256,256)
    const float* Pos    = (const float*)d_in[1];  // (128,3,256,256)
    const float* meanp  = (const float*)d_in[2];  // (3,256,256)
    const int*   uv     = (const int*)  d_in[3];  // (68,2)
    float* out = (float*)d_out;

    kabsch_kernel<<<BATCH, 128>>>(Offset, Pos, meanp, uv);

    dim3 grid(HW / 4 / 256, BATCH);
    apply_kernel<<<grid, 256>>>((const float4*)Offset, (const float4*)meanp, (float4*)out);
}

// round 3
// speedup vs baseline: 5.2103x; 1.9034x over previous
#include <cuda_runtime.h>
#include <cuda_bf16.h>
#include <math.h>

#define BATCH 128
#define HH 256
#define WW 256
#define HW (HH*WW)
#define NK 68
#define OFFSET_SCALE 6.0f

// per-batch transform params: M[0..8] row-major (e,d), t[9..11]
__device__ float g_par[BATCH][12];

__device__ __forceinline__ float warp_sum(float v) {
    #pragma unroll
    for (int m = 16; m > 0; m >>= 1)
        v += __shfl_xor_sync(0xffffffffu, v, m);
    return v;   // every lane has the full sum
}

// ---------------------------------------------------------------------------
// Kernel 1: per-batch Kabsch, one warp per batch, shuffle reductions only
// ---------------------------------------------------------------------------
__global__ void __launch_bounds__(256) kabsch_kernel(
    const float* __restrict__ Offset,
    const float* __restrict__ Pos,
    const float* __restrict__ meanp,
    const int*   __restrict__ uv)
{
    const int warp = threadIdx.x >> 5;
    const int lane = threadIdx.x & 31;
    const int b    = blockIdx.x * 8 + warp;   // 16 blocks * 8 warps = 128

    const float* ob = Offset + (size_t)b * 3 * HW;
    const float* pb = Pos    + (size_t)b * 3 * HW;

    // each lane owns points lane, lane+32, lane+64 (inactive slots zero-weight)
    float src[3][3], dst[3][3];
    bool  act[3];
    #pragma unroll
    for (int j = 0; j < 3; j++) {
        int i = lane + 32*j;
        act[j] = (i < NK);
        int ii = act[j] ? i : 0;
        int u0 = __ldg(&uv[2*ii]);
        int u1 = __ldg(&uv[2*ii + 1]);
        int idx = u0 * WW + u1;
        #pragma unroll
        for (int c = 0; c < 3; c++) {
            src[j][c] = fmaf(__ldg(&ob[c*HW + idx]), OFFSET_SCALE, __ldg(&meanp[c*HW + idx]));
            dst[j][c] = __ldg(&pb[c*HW + idx]);
        }
    }

    // broadcast point 0 (lane 0, j=0)
    float s0[3], d0[3];
    #pragma unroll
    for (int c = 0; c < 3; c++) {
        s0[c] = __shfl_sync(0xffffffffu, src[0][c], 0);
        d0[c] = __shfl_sync(0xffffffffu, dst[0][c], 0);
    }

    // phase 1: s1, s2, sums (8 scalars)
    float a_s1 = 0.f, a_s2 = 0.f;
    float a_ss[3] = {0.f,0.f,0.f}, a_sd[3] = {0.f,0.f,0.f};
    #pragma unroll
    for (int j = 0; j < 3; j++) {
        if (act[j]) {
            float dsx = src[j][0]-s0[0], dsy = src[j][1]-s0[1], dsz = src[j][2]-s0[2];
            float ddx = dst[j][0]-d0[0], ddy = dst[j][1]-d0[1], ddz = dst[j][2]-d0[2];
            a_s1 += sqrtf(fmaf(dsx,dsx, fmaf(dsy,dsy, dsz*dsz)));
            a_s2 += sqrtf(fmaf(ddx,ddx, fmaf(ddy,ddy, ddz*ddz)));
            #pragma unroll
            for (int c = 0; c < 3; c++) { a_ss[c] += src[j][c]; a_sd[c] += dst[j][c]; }
        }
    }
    float s1 = warp_sum(a_s1);
    float s2 = warp_sum(a_s2);
    float msrc[3], mdst[3];
    #pragma unroll
    for (int c = 0; c < 3; c++) {
        msrc[c] = warp_sum(a_ss[c]) * (1.0f / NK);
        mdst[c] = warp_sum(a_sd[c]) * (1.0f / NK);
    }
    float scale = __fdividef(s2, s1);

    // phase 2: X[e][d] = sum_i (dst_i - mdst)[e] * (src_i - msrc)[d]   (= H^T)
    float ax[9] = {0,0,0,0,0,0,0,0,0};
    #pragma unroll
    for (int j = 0; j < 3; j++) {
        if (act[j]) {
            float sd[3], dd[3];
            #pragma unroll
            for (int c = 0; c < 3; c++) { sd[c] = src[j][c]-msrc[c]; dd[c] = dst[j][c]-mdst[c]; }
            #pragma unroll
            for (int e = 0; e < 3; e++)
                #pragma unroll
                for (int d = 0; d < 3; d++)
                    ax[e*3+d] = fmaf(dd[e], sd[d], ax[e*3+d]);
        }
    }
    float q[9];
    #pragma unroll
    for (int i = 0; i < 9; i++) q[i] = warp_sum(ax[i]);

    // Newton polar iteration with gamma scaling (all lanes redundantly):
    //   Q <- 0.5*(g*Q + (1/g)*Q^{-T}),  g = (||Q^{-1}||_F/||Q||_F)^{1/2}
    // Converges to the orthogonal polar factor of X = H^T == Kabsch R = V U^T.
    #pragma unroll 1
    for (int it = 0; it < 14; it++) {
        float c00 =  q[4]*q[8] - q[5]*q[7];
        float c01 = -(q[3]*q[8] - q[5]*q[6]);
        float c02 =  q[3]*q[7] - q[4]*q[6];
        float det = q[0]*c00 + q[1]*c01 + q[2]*c02;
        float rdet = __fdividef(1.0f, det);
        float inv[9];
        inv[0] =  c00 * rdet;
        inv[1] = (q[2]*q[7] - q[1]*q[8]) * rdet;
        inv[2] = (q[1]*q[5] - q[2]*q[4]) * rdet;
        inv[3] =  c01 * rdet;
        inv[4] = (q[0]*q[8] - q[2]*q[6]) * rdet;
        inv[5] = (q[2]*q[3] - q[0]*q[5]) * rdet;
        inv[6] =  c02 * rdet;
        inv[7] = (q[1]*q[6] - q[0]*q[7]) * rdet;
        inv[8] = (q[0]*q[4] - q[1]*q[3]) * rdet;

        float nq = 0.f, ni = 0.f;
        #pragma unroll
        for (int i = 0; i < 9; i++) { nq = fmaf(q[i], q[i], nq); ni = fmaf(inv[i], inv[i], ni); }
        float g  = sqrtf(sqrtf(__fdividef(ni, nq)));
        float gi = 0.5f * __frcp_rn(g);
        g *= 0.5f;
        float nq2[9];
        #pragma unroll
        for (int r = 0; r < 3; r++)
            #pragma unroll
            for (int c = 0; c < 3; c++)
                nq2[r*3+c] = fmaf(g, q[r*3+c], gi * inv[c*3+r]);
        #pragma unroll
        for (int i = 0; i < 9; i++) q[i] = nq2[i];
    }

    // params: M = scale*R (9), t (3). lanes 0..11 write.
    float par;
    if (lane < 9) {
        par = scale * q[lane];
    } else {
        int e = lane - 9;
        par = mdst[e] - scale * (q[e*3+0]*msrc[0] + q[e*3+1]*msrc[1] + q[e*3+2]*msrc[2]);
    }
    if (lane < 12) g_par[b][lane] = par;
}

// ---------------------------------------------------------------------------
// Kernel 2: apply affine transform to all pixels (float4-vectorized, streaming)
// out[b,e,p] = sum_d M[e][d] * (6*Offset[b,d,p] + mean[d,p]) + t[e]
// ---------------------------------------------------------------------------
__global__ void __launch_bounds__(256) apply_kernel(
    const float4* __restrict__ Offset,
    const float4* __restrict__ meanp,
    float4* __restrict__ out)
{
    const int b = blockIdx.y;
    const int i = blockIdx.x * blockDim.x + threadIdx.x;  // 0 .. HW/4-1

    __shared__ float sP[12];
    if (threadIdx.x < 12) sP[threadIdx.x] = g_par[b][threadIdx.x];
    __syncthreads();

    const int planeQ = HW / 4;
    const size_t base = (size_t)b * 3 * planeQ;

    float4 o0 = Offset[base + 0*planeQ + i];
    float4 o1 = Offset[base + 1*planeQ + i];
    float4 o2 = Offset[base + 2*planeQ + i];
    float4 m0 = meanp[0*planeQ + i];
    float4 m1 = meanp[1*planeQ + i];
    float4 m2 = meanp[2*planeQ + i];

    float4 p0, p1, p2;
    p0.x = fmaf(o0.x, OFFSET_SCALE, m0.x); p0.y = fmaf(o0.y, OFFSET_SCALE, m0.y);
    p0.z = fmaf(o0.z, OFFSET_SCALE, m0.z); p0.w = fmaf(o0.w, OFFSET_SCALE, m0.w);
    p1.x = fmaf(o1.x, OFFSET_SCALE, m1.x); p1.y = fmaf(o1.y, OFFSET_SCALE, m1.y);
    p1.z = fmaf(o1.z, OFFSET_SCALE, m1.z); p1.w = fmaf(o1.w, OFFSET_SCALE, m1.w);
    p2.x = fmaf(o2.x, OFFSET_SCALE, m2.x); p2.y = fmaf(o2.y, OFFSET_SCALE, m2.y);
    p2.z = fmaf(o2.z, OFFSET_SCALE, m2.z); p2.w = fmaf(o2.w, OFFSET_SCALE, m2.w);

    #pragma unroll
    for (int e = 0; e < 3; e++) {
        float a = sP[e*3+0], bb = sP[e*3+1], cc = sP[e*3+2], t = sP[9+e];
        float4 r;
        r.x = fmaf(a, p0.x, fmaf(bb, p1.x, fmaf(cc, p2.x, t)));
        r.y = fmaf(a, p0.y, fmaf(bb, p1.y, fmaf(cc, p2.y, t)));
        r.z = fmaf(a, p0.z, fmaf(bb, p1.z, fmaf(cc, p2.z, t)));
        r.w = fmaf(a, p0.w, fmaf(bb, p1.w, fmaf(cc, p2.w, t)));
        out[base + e*planeQ + i] = r;
    }
}

// ---------------------------------------------------------------------------
extern "C" void kernel_launch(void* const* d_in, const int* in_sizes, int n_in,
                              void* d_out, int out_size)
{
    const float* Offset = (const float*)d_in[0];  // (128,3,256,256)
    const float* Pos    = (const float*)d_in[1];  // (128,3,256,256)
    const float* meanp  = (const float*)d_in[2];  // (3,256,256)
    const int*   uv     = (const int*)  d_in[3];  // (68,2)
    float* out = (float*)d_out;

    kabsch_kernel<<<16, 256>>>(Offset, Pos, meanp, uv);

    dim3 grid(HW / 4 / 256, BATCH);
    apply_kernel<<<grid, 256>>>((const float4*)Offset, (const float4*)meanp, (float4*)out);
}

// round 4
// speedup vs baseline: 5.4533x; 1.0467x over previous
#include <cuda_runtime.h>
#include <cuda_bf16.h>
#include <math.h>

#define BATCH 128
#define HH 256
#define WW 256
#define HW (HH*WW)
#define NK 68
#define OFFSET_SCALE 6.0f

// per-batch transform params: M[0..8] row-major (e,d), t[9..11]
__device__ float g_par[BATCH][12];

__device__ __forceinline__ float warp_sum(float v) {
    #pragma unroll
    for (int m = 16; m > 0; m >>= 1)
        v += __shfl_xor_sync(0xffffffffu, v, m);
    return v;   // every lane has the full sum
}

// ---------------------------------------------------------------------------
// Kernel 1: per-batch Kabsch, one warp per block (128 blocks), shuffle-only
// ---------------------------------------------------------------------------
__global__ void __launch_bounds__(32) kabsch_kernel(
    const float* __restrict__ Offset,
    const float* __restrict__ Pos,
    const float* __restrict__ meanp,
    const int*   __restrict__ uv)
{
    // let the dependent apply_kernel start launching right away
    cudaTriggerProgrammaticLaunchCompletion();

    const int lane = threadIdx.x & 31;
    const int b    = blockIdx.x;

    const float* ob = Offset + (size_t)b * 3 * HW;
    const float* pb = Pos    + (size_t)b * 3 * HW;

    // each lane owns points lane, lane+32, lane+64 (inactive slots zero-weight)
    float src[3][3], dst[3][3];
    bool  act[3];
    #pragma unroll
    for (int j = 0; j < 3; j++) {
        int i = lane + 32*j;
        act[j] = (i < NK);
        int ii = act[j] ? i : 0;
        int u0 = __ldg(&uv[2*ii]);
        int u1 = __ldg(&uv[2*ii + 1]);
        int idx = u0 * WW + u1;
        #pragma unroll
        for (int c = 0; c < 3; c++) {
            src[j][c] = fmaf(__ldg(&ob[c*HW + idx]), OFFSET_SCALE, __ldg(&meanp[c*HW + idx]));
            dst[j][c] = __ldg(&pb[c*HW + idx]);
        }
    }

    // broadcast point 0 (lane 0, j=0)
    float s0[3], d0[3];
    #pragma unroll
    for (int c = 0; c < 3; c++) {
        s0[c] = __shfl_sync(0xffffffffu, src[0][c], 0);
        d0[c] = __shfl_sync(0xffffffffu, dst[0][c], 0);
    }

    // phase 1: s1, s2, sums
    float a_s1 = 0.f, a_s2 = 0.f;
    float a_ss[3] = {0.f,0.f,0.f}, a_sd[3] = {0.f,0.f,0.f};
    #pragma unroll
    for (int j = 0; j < 3; j++) {
        if (act[j]) {
            float dsx = src[j][0]-s0[0], dsy = src[j][1]-s0[1], dsz = src[j][2]-s0[2];
            float ddx = dst[j][0]-d0[0], ddy = dst[j][1]-d0[1], ddz = dst[j][2]-d0[2];
            a_s1 += sqrtf(fmaf(dsx,dsx, fmaf(dsy,dsy, dsz*dsz)));
            a_s2 += sqrtf(fmaf(ddx,ddx, fmaf(ddy,ddy, ddz*ddz)));
            #pragma unroll
            for (int c = 0; c < 3; c++) { a_ss[c] += src[j][c]; a_sd[c] += dst[j][c]; }
        }
    }
    float s1 = warp_sum(a_s1);
    float s2 = warp_sum(a_s2);
    float msrc[3], mdst[3];
    #pragma unroll
    for (int c = 0; c < 3; c++) {
        msrc[c] = warp_sum(a_ss[c]) * (1.0f / NK);
        mdst[c] = warp_sum(a_sd[c]) * (1.0f / NK);
    }
    float scale = __fdividef(s2, s1);

    // phase 2: X[e][d] = sum_i (dst_i - mdst)[e] * (src_i - msrc)[d]   (= H^T)
    float ax[9] = {0,0,0,0,0,0,0,0,0};
    #pragma unroll
    for (int j = 0; j < 3; j++) {
        if (act[j]) {
            float sd[3], dd[3];
            #pragma unroll
            for (int c = 0; c < 3; c++) { sd[c] = src[j][c]-msrc[c]; dd[c] = dst[j][c]-mdst[c]; }
            #pragma unroll
            for (int e = 0; e < 3; e++)
                #pragma unroll
                for (int d = 0; d < 3; d++)
                    ax[e*3+d] = fmaf(dd[e], sd[d], ax[e*3+d]);
        }
    }
    float q[9];
    #pragma unroll
    for (int i = 0; i < 9; i++) q[i] = warp_sum(ax[i]);

    // Newton polar iteration with gamma scaling (all lanes redundantly):
    //   Q <- 0.5*(g*Q + (1/g)*Q^{-T}) -> orthogonal polar factor of H^T == V U^T
    #pragma unroll 1
    for (int it = 0; it < 14; it++) {
        float c00 =  q[4]*q[8] - q[5]*q[7];
        float c01 = -(q[3]*q[8] - q[5]*q[6]);
        float c02 =  q[3]*q[7] - q[4]*q[6];
        float det = q[0]*c00 + q[1]*c01 + q[2]*c02;
        float rdet = __fdividef(1.0f, det);
        float inv[9];
        inv[0] =  c00 * rdet;
        inv[1] = (q[2]*q[7] - q[1]*q[8]) * rdet;
        inv[2] = (q[1]*q[5] - q[2]*q[4]) * rdet;
        inv[3] =  c01 * rdet;
        inv[4] = (q[0]*q[8] - q[2]*q[6]) * rdet;
        inv[5] = (q[2]*q[3] - q[0]*q[5]) * rdet;
        inv[6] =  c02 * rdet;
        inv[7] = (q[1]*q[6] - q[0]*q[7]) * rdet;
        inv[8] = (q[0]*q[4] - q[1]*q[3]) * rdet;

        float nq = 0.f, ni = 0.f;
        #pragma unroll
        for (int i = 0; i < 9; i++) { nq = fmaf(q[i], q[i], nq); ni = fmaf(inv[i], inv[i], ni); }
        float g  = sqrtf(sqrtf(__fdividef(ni, nq)));
        float gi = 0.5f * __frcp_rn(g);
        g *= 0.5f;
        float nq2[9];
        #pragma unroll
        for (int r = 0; r < 3; r++)
            #pragma unroll
            for (int c = 0; c < 3; c++)
                nq2[r*3+c] = fmaf(g, q[r*3+c], gi * inv[c*3+r]);
        #pragma unroll
        for (int i = 0; i < 9; i++) q[i] = nq2[i];
    }

    float par;
    if (lane < 9) {
        par = scale * q[lane];
    } else {
        int e = lane - 9;
        par = mdst[e] - scale * (q[e*3+0]*msrc[0] + q[e*3+1]*msrc[1] + q[e*3+2]*msrc[2]);
    }
    if (lane < 12) g_par[b][lane] = par;
}

// ---------------------------------------------------------------------------
// Kernel 2: apply affine transform (PDL consumer).
// Issues all streaming loads BEFORE the grid dependency sync so the DRAM
// latency overlaps the wait for kabsch_kernel completion.
// ---------------------------------------------------------------------------
__global__ void __launch_bounds__(256) apply_kernel(
    const float4* __restrict__ Offset,
    const float4* __restrict__ meanp,
    float4* __restrict__ out)
{
    const int b = blockIdx.y;
    const int i = blockIdx.x * blockDim.x + threadIdx.x;  // 0 .. HW/4-1

    const int planeQ = HW / 4;
    const size_t base = (size_t)b * 3 * planeQ;

    // independent work first: issue all 6 loads (non-blocking until use)
    float4 o0 = Offset[base + 0*planeQ + i];
    float4 o1 = Offset[base + 1*planeQ + i];
    float4 o2 = Offset[base + 2*planeQ + i];
    float4 m0 = meanp[0*planeQ + i];
    float4 m1 = meanp[1*planeQ + i];
    float4 m2 = meanp[2*planeQ + i];

    // wait for kabsch_kernel grid to complete (params visible after this)
    cudaGridDependencySynchronize();

    __shared__ float sP[12];
    if (threadIdx.x < 12) sP[threadIdx.x] = g_par[b][threadIdx.x];
    __syncthreads();

    float4 p0, p1, p2;
    p0.x = fmaf(o0.x, OFFSET_SCALE, m0.x); p0.y = fmaf(o0.y, OFFSET_SCALE, m0.y);
    p0.z = fmaf(o0.z, OFFSET_SCALE, m0.z); p0.w = fmaf(o0.w, OFFSET_SCALE, m0.w);
    p1.x = fmaf(o1.x, OFFSET_SCALE, m1.x); p1.y = fmaf(o1.y, OFFSET_SCALE, m1.y);
    p1.z = fmaf(o1.z, OFFSET_SCALE, m1.z); p1.w = fmaf(o1.w, OFFSET_SCALE, m1.w);
    p2.x = fmaf(o2.x, OFFSET_SCALE, m2.x); p2.y = fmaf(o2.y, OFFSET_SCALE, m2.y);
    p2.z = fmaf(o2.z, OFFSET_SCALE, m2.z); p2.w = fmaf(o2.w, OFFSET_SCALE, m2.w);

    #pragma unroll
    for (int e = 0; e < 3; e++) {
        float a = sP[e*3+0], bb = sP[e*3+1], cc = sP[e*3+2], t = sP[9+e];
        float4 r;
        r.x = fmaf(a, p0.x, fmaf(bb, p1.x, fmaf(cc, p2.x, t)));
        r.y = fmaf(a, p0.y, fmaf(bb, p1.y, fmaf(cc, p2.y, t)));
        r.z = fmaf(a, p0.z, fmaf(bb, p1.z, fmaf(cc, p2.z, t)));
        r.w = fmaf(a, p0.w, fmaf(bb, p1.w, fmaf(cc, p2.w, t)));
        out[base + e*planeQ + i] = r;
    }
}

// ---------------------------------------------------------------------------
extern "C" void kernel_launch(void* const* d_in, const int* in_sizes, int n_in,
                              void* d_out, int out_size)
{
    const float* Offset = (const float*)d_in[0];  // (128,3,256,256)
    const float* Pos    = (const float*)d_in[1];  // (128,3,256,256)
    const float* meanp  = (const float*)d_in[2];  // (3,256,256)
    const int*   uv     = (const int*)  d_in[3];  // (68,2)
    float* out = (float*)d_out;

    kabsch_kernel<<<BATCH, 32>>>(Offset, Pos, meanp, uv);

    // apply_kernel with programmatic dependent launch: overlaps its prologue
    // (streaming loads) with kabsch_kernel's tail.
    cudaLaunchConfig_t cfg = {};
    cfg.gridDim  = dim3(HW / 4 / 256, BATCH, 1);
    cfg.blockDim = dim3(256, 1, 1);
    cfg.dynamicSmemBytes = 0;
    cfg.stream = 0;
    cudaLaunchAttribute attr[1];
    attr[0].id = cudaLaunchAttributeProgrammaticStreamSerialization;
    attr[0].val.programmaticStreamSerializationAllowed = 1;
    cfg.attrs = attr;
    cfg.numAttrs = 1;
    cudaLaunchKernelEx(&cfg, apply_kernel,
                       (const float4*)Offset, (const float4*)meanp, (float4*)out);
}